// round 1
// baseline (speedup 1.0000x reference)
#include <cuda_runtime.h>
#include <math.h>

#define B_ 8
#define M_ 1024
#define D_ 1024
#define H_ 16
#define F_ 4096
#define NLAYERS 4
#define DK_ 64
#define ROWS (B_*M_)   // 8192

// ---------------- scratch (device globals; no allocation) ----------------
__device__ float g_x  [ROWS * D_];
__device__ float g_q  [ROWS * D_];
__device__ float g_k  [ROWS * D_];
__device__ float g_v  [ROWS * D_];
__device__ float g_o  [ROWS * D_];
__device__ float g_ffn[ROWS * F_];   // also reused as attention output buffer

__device__ __forceinline__ float gelu_exact(float x) {
    return 0.5f * x * (1.0f + erff(x * 0.70710678118654752f));
}

// ---------------- SGEMM: C = A(MxK) @ W(KxN) + bias, optional GELU -------
// 128x128 tile, BK=16, 256 threads, 8x8 microtile (split 4 + 64-offset 4)
template<bool GELU>
__global__ __launch_bounds__(256) void sgemm_bias(
    const float* __restrict__ A, const float* __restrict__ W,
    const float* __restrict__ bias, float* __restrict__ C,
    int Kdim, int Ncols)
{
    __shared__ float As[16][132];
    __shared__ float Bs[16][128];

    const int tid = threadIdx.x;
    const int m0 = blockIdx.y * 128;
    const int n0 = blockIdx.x * 128;
    const int ty = tid >> 4;       // 0..15
    const int tx = tid & 15;       // 0..15

    float acc[8][8];
#pragma unroll
    for (int i = 0; i < 8; i++)
#pragma unroll
        for (int j = 0; j < 8; j++) acc[i][j] = 0.0f;

    const int ar = tid >> 2;       // 0..63
    const int ac = tid & 3;        // 0..3
    const int br = tid >> 5;       // 0..7
    const int bc = tid & 31;       // 0..31

    const float* Aload = A + (size_t)(m0 + ar) * Kdim + ac * 4;
    const float* Bload = W + (size_t)br * Ncols + n0 + bc * 4;

    for (int k0 = 0; k0 < Kdim; k0 += 16) {
#pragma unroll
        for (int p = 0; p < 2; p++) {
            float4 av = *(const float4*)(Aload + (size_t)(p * 64) * Kdim + k0);
            As[ac * 4 + 0][ar + p * 64] = av.x;
            As[ac * 4 + 1][ar + p * 64] = av.y;
            As[ac * 4 + 2][ar + p * 64] = av.z;
            As[ac * 4 + 3][ar + p * 64] = av.w;
        }
#pragma unroll
        for (int p = 0; p < 2; p++) {
            float4 bv = *(const float4*)(Bload + (size_t)(k0 + p * 8) * Ncols);
            *(float4*)&Bs[br + p * 8][bc * 4] = bv;
        }
        __syncthreads();

#pragma unroll
        for (int kk = 0; kk < 16; kk++) {
            float a[8], bb[8];
            *(float4*)&a[0]  = *(const float4*)&As[kk][ty * 4];
            *(float4*)&a[4]  = *(const float4*)&As[kk][64 + ty * 4];
            *(float4*)&bb[0] = *(const float4*)&Bs[kk][tx * 4];
            *(float4*)&bb[4] = *(const float4*)&Bs[kk][64 + tx * 4];
#pragma unroll
            for (int i = 0; i < 8; i++)
#pragma unroll
                for (int j = 0; j < 8; j++)
                    acc[i][j] = fmaf(a[i], bb[j], acc[i][j]);
        }
        __syncthreads();
    }

#pragma unroll
    for (int i = 0; i < 8; i++) {
        const int rr = m0 + ((i < 4) ? (ty * 4 + i) : (64 + ty * 4 + i - 4));
#pragma unroll
        for (int jg = 0; jg < 2; jg++) {
            const int cc = n0 + jg * 64 + tx * 4;
            float r0 = acc[i][jg * 4 + 0] + bias[cc + 0];
            float r1 = acc[i][jg * 4 + 1] + bias[cc + 1];
            float r2 = acc[i][jg * 4 + 2] + bias[cc + 2];
            float r3 = acc[i][jg * 4 + 3] + bias[cc + 3];
            if (GELU) {
                r0 = gelu_exact(r0); r1 = gelu_exact(r1);
                r2 = gelu_exact(r2); r3 = gelu_exact(r3);
            }
            *(float4*)&C[(size_t)rr * Ncols + cc] = make_float4(r0, r1, r2, r3);
        }
    }
}

// ---------------- Flash attention (fp32, online softmax) -----------------
// grid: (M/64, B*H), block 256. Each CTA: 64 q rows x DK=64, loops k tiles.
__global__ __launch_bounds__(256) void flash_attn(
    const float* __restrict__ q, const float* __restrict__ k,
    const float* __restrict__ v, const float* __restrict__ w,
    float* __restrict__ o)
{
    __shared__ float Qs[64][68];
    __shared__ float Kt[64][68];   // [d][kcol]
    __shared__ float Vs[64][68];
    __shared__ float Ps[64][68];

    const int b  = blockIdx.y >> 4;
    const int h  = blockIdx.y & 15;
    const int q0 = blockIdx.x * 64;
    const int tid = threadIdx.x;
    const int ty = tid >> 4;       // 0..15 -> rows ty*4..+3
    const int tx = tid & 15;       // 0..15 -> cols tx*4..+3
    const int hoff = h * DK_;

    const float* qbase = q + (size_t)b * M_ * D_ + hoff;
    const float* kbase = k + (size_t)b * M_ * D_ + hoff;
    const float* vbase = v + (size_t)b * M_ * D_ + hoff;
    const float* wbase = w + (size_t)b * M_;

    for (int idx = tid; idx < 64 * 64; idx += 256) {
        int r = idx >> 6, c = idx & 63;
        Qs[r][c] = qbase[(size_t)(q0 + r) * D_ + c];
    }

    float m_i[4], l_i[4], oacc[4][4];
#pragma unroll
    for (int i = 0; i < 4; i++) {
        m_i[i] = -1e30f; l_i[i] = 0.0f;
#pragma unroll
        for (int j = 0; j < 4; j++) oacc[i][j] = 0.0f;
    }
    __syncthreads();

    for (int kb = 0; kb < M_; kb += 64) {
        for (int idx = tid; idx < 64 * 64; idx += 256) {
            int r = idx >> 6, c = idx & 63;
            float kv = kbase[(size_t)(kb + r) * D_ + c];
            Kt[c][r] = kv;
            Vs[r][c] = vbase[(size_t)(kb + r) * D_ + c];
        }
        __syncthreads();

        float s[4][4];
#pragma unroll
        for (int i = 0; i < 4; i++)
#pragma unroll
            for (int j = 0; j < 4; j++) s[i][j] = 0.0f;

#pragma unroll 8
        for (int d = 0; d < 64; d++) {
            float a[4], bb[4];
#pragma unroll
            for (int i = 0; i < 4; i++) a[i] = Qs[ty * 4 + i][d];
#pragma unroll
            for (int j = 0; j < 4; j++) bb[j] = Kt[d][tx * 4 + j];
#pragma unroll
            for (int i = 0; i < 4; i++)
#pragma unroll
                for (int j = 0; j < 4; j++)
                    s[i][j] = fmaf(a[i], bb[j], s[i][j]);
        }

        float wj[4];
#pragma unroll
        for (int j = 0; j < 4; j++) wj[j] = wbase[kb + tx * 4 + j];
#pragma unroll
        for (int i = 0; i < 4; i++)
#pragma unroll
            for (int j = 0; j < 4; j++)
                s[i][j] = s[i][j] * 0.125f + wj[j];

#pragma unroll
        for (int i = 0; i < 4; i++) {
            float rmax = fmaxf(fmaxf(s[i][0], s[i][1]), fmaxf(s[i][2], s[i][3]));
#pragma unroll
            for (int off = 8; off > 0; off >>= 1)
                rmax = fmaxf(rmax, __shfl_xor_sync(0xffffffffu, rmax, off, 16));
            float mnew = fmaxf(m_i[i], rmax);
            float corr = __expf(m_i[i] - mnew);
            float rsum = 0.0f;
#pragma unroll
            for (int j = 0; j < 4; j++) {
                s[i][j] = __expf(s[i][j] - mnew);
                rsum += s[i][j];
            }
#pragma unroll
            for (int off = 8; off > 0; off >>= 1)
                rsum += __shfl_xor_sync(0xffffffffu, rsum, off, 16);
            l_i[i] = l_i[i] * corr + rsum;
            m_i[i] = mnew;
#pragma unroll
            for (int j = 0; j < 4; j++) oacc[i][j] *= corr;
#pragma unroll
            for (int j = 0; j < 4; j++) Ps[ty * 4 + i][tx * 4 + j] = s[i][j];
        }
        __syncthreads();

#pragma unroll 8
        for (int kk = 0; kk < 64; kk++) {
            float pr[4], vr[4];
#pragma unroll
            for (int i = 0; i < 4; i++) pr[i] = Ps[ty * 4 + i][kk];
#pragma unroll
            for (int j = 0; j < 4; j++) vr[j] = Vs[kk][tx * 4 + j];
#pragma unroll
            for (int i = 0; i < 4; i++)
#pragma unroll
                for (int j = 0; j < 4; j++)
                    oacc[i][j] = fmaf(pr[i], vr[j], oacc[i][j]);
        }
        __syncthreads();
    }

#pragma unroll
    for (int i = 0; i < 4; i++) {
        float inv = 1.0f / l_i[i];
        float4 ov = make_float4(oacc[i][0] * inv, oacc[i][1] * inv,
                                oacc[i][2] * inv, oacc[i][3] * inv);
        *(float4*)&o[(size_t)(b * M_ + q0 + ty * 4 + i) * D_ + hoff + tx * 4] = ov;
    }
}

// ---------------- fused residual add + LayerNorm -------------------------
__device__ __forceinline__ float block_sum256(float val, float* red) {
    const int lane = threadIdx.x & 31;
    const int wid  = threadIdx.x >> 5;
#pragma unroll
    for (int o = 16; o > 0; o >>= 1) val += __shfl_xor_sync(0xffffffffu, val, o);
    if (lane == 0) red[wid] = val;
    __syncthreads();
    float t = (threadIdx.x < 8) ? red[threadIdx.x] : 0.0f;
    if (wid == 0) {
#pragma unroll
        for (int o = 4; o > 0; o >>= 1) t += __shfl_xor_sync(0xffffffffu, t, o);
        if (lane == 0) red[0] = t;
    }
    __syncthreads();
    float r = red[0];
    __syncthreads();
    return r;
}

__global__ __launch_bounds__(256) void add_ln(
    const float* __restrict__ xin, const float* __restrict__ del,
    const float* __restrict__ g, const float* __restrict__ be,
    float* __restrict__ xout)
{
    __shared__ float red[8];
    const int row = blockIdx.x;
    const int tid = threadIdx.x;
    const float* xr = xin + (size_t)row * D_;
    const float* dr = del + (size_t)row * D_;

    float v[4];
    float s = 0.0f;
#pragma unroll
    for (int u = 0; u < 4; u++) {
        v[u] = xr[tid + u * 256] + dr[tid + u * 256];
        s += v[u];
    }
    float tot = block_sum256(s, red);
    float mu = tot * (1.0f / D_);
    float qs = 0.0f;
#pragma unroll
    for (int u = 0; u < 4; u++) {
        float d = v[u] - mu;
        qs += d * d;
    }
    float var = block_sum256(qs, red) * (1.0f / D_);
    float rstd = rsqrtf(var + 1e-5f);
#pragma unroll
    for (int u = 0; u < 4; u++) {
        int c = tid + u * 256;
        xout[(size_t)row * D_ + c] = (v[u] - mu) * rstd * g[c] + be[c];
    }
}

// ---------------- driver --------------------------------------------------
extern "C" void kernel_launch(void* const* d_in, const int* in_sizes, int n_in,
                              void* d_out, int out_size) {
    const float* embeds  = (const float*)d_in[0];
    const float* weights = (const float*)d_in[1];
    const float* Wq = (const float*)d_in[2];
    const float* bq = (const float*)d_in[3];
    const float* Wk = (const float*)d_in[4];
    const float* bk = (const float*)d_in[5];
    const float* Wv = (const float*)d_in[6];
    const float* bv = (const float*)d_in[7];
    const float* Wo = (const float*)d_in[8];
    const float* bo = (const float*)d_in[9];
    const float* W1 = (const float*)d_in[10];
    const float* b1 = (const float*)d_in[11];
    const float* W2 = (const float*)d_in[12];
    const float* b2 = (const float*)d_in[13];
    const float* g1 = (const float*)d_in[14];
    const float* be1= (const float*)d_in[15];
    const float* g2 = (const float*)d_in[16];
    const float* be2= (const float*)d_in[17];

    float *px, *pq, *pk, *pv, *po, *pffn;
    cudaGetSymbolAddress((void**)&px,   g_x);
    cudaGetSymbolAddress((void**)&pq,   g_q);
    cudaGetSymbolAddress((void**)&pk,   g_k);
    cudaGetSymbolAddress((void**)&pv,   g_v);
    cudaGetSymbolAddress((void**)&po,   g_o);
    cudaGetSymbolAddress((void**)&pffn, g_ffn);

    cudaMemcpyAsync(px, embeds, sizeof(float) * (size_t)ROWS * D_,
                    cudaMemcpyDeviceToDevice);

    const dim3 gD(D_ / 128, ROWS / 128);   // (8, 64)
    const dim3 gF(F_ / 128, ROWS / 128);   // (32, 64)
    const dim3 gA(M_ / 64, B_ * H_);       // (16, 128)

    for (int l = 0; l < NLAYERS; l++) {
        const float* wq = Wq + (size_t)l * D_ * D_;
        const float* wk = Wk + (size_t)l * D_ * D_;
        const float* wv = Wv + (size_t)l * D_ * D_;
        const float* wo = Wo + (size_t)l * D_ * D_;
        const float* w1 = W1 + (size_t)l * D_ * F_;
        const float* w2 = W2 + (size_t)l * F_ * D_;

        sgemm_bias<false><<<gD, 256>>>(px, wq, bq + (size_t)l * D_, pq, D_, D_);
        sgemm_bias<false><<<gD, 256>>>(px, wk, bk + (size_t)l * D_, pk, D_, D_);
        sgemm_bias<false><<<gD, 256>>>(px, wv, bv + (size_t)l * D_, pv, D_, D_);

        flash_attn<<<gA, 256>>>(pq, pk, pv, weights, pffn);

        sgemm_bias<false><<<gD, 256>>>(pffn, wo, bo + (size_t)l * D_, po, D_, D_);
        add_ln<<<ROWS, 256>>>(px, po, g1 + (size_t)l * D_, be1 + (size_t)l * D_, px);

        sgemm_bias<true><<<gF, 256>>>(px, w1, b1 + (size_t)l * F_, pffn, D_, F_);
        sgemm_bias<false><<<gD, 256>>>(pffn, w2, b2 + (size_t)l * D_, po, F_, D_);
        add_ln<<<ROWS, 256>>>(px, po, g2 + (size_t)l * D_, be2 + (size_t)l * D_, px);
    }

    cudaMemcpyAsync(d_out, px, sizeof(float) * (size_t)ROWS * D_,
                    cudaMemcpyDeviceToDevice);
}